// round 9
// baseline (speedup 1.0000x reference)
#include <cuda_runtime.h>
#include <cuda_fp16.h>
#include <stdint.h>

// ---------------- Problem shape ----------------
#define BB 8
#define NN 3136
#define DD 1536
#define PP 4096
#define MM (BB*NN)          // 25088

// ---------------- Tiling ----------------
#define BM 256
#define BN 256
#define BK 64               // fp16 per k-chunk (128 B rows)
#define NKC (DD/BK)         // 24
#define NMT (MM/BM)         // 98
#define NNT (PP/BN)         // 16
#define NITEMS (NMT*NNT)    // 1568
#define GRID 148            // 1 persistent 512-thread CTA per SM
#define THREADS 512
#define NSTAGE 3

#define STAGE_BYTES ((BM+BN)*BK*2)           // 65536
#define SMEM_BYTES (NSTAGE*STAGE_BYTES)      // 196608

// ---------------- Scratch (device globals: allocation-free rule) ------------
__device__ __half g_A[(size_t)MM*DD];          // embeds f16
__device__ __half g_Bc[(size_t)PP*DD];         // centroids f16
__device__ float g_nA[MM];                     // ||x||^2 (fp32 from fp32 inputs)
__device__ float g_nB[PP];                     // ||c||^2
__device__ unsigned int g_min[MM];             // running min of dist^2 (uint bits)

// ---------------------------------------------------------------------------
// Prep: fp32 -> fp16 (vectorized) + fp32 squared norms + g_min init.
// ---------------------------------------------------------------------------
#define PT 128
__global__ void prep_kernel(const float* __restrict__ embeds,
                            const float* __restrict__ cents,
                            float* __restrict__ out, int loss_elems) {
    int row = blockIdx.x;
    const float4* src;
    uint2* dst;
    float* ndst;
    if (row < MM) {
        src = (const float4*)(embeds + (size_t)row * DD);
        dst = (uint2*)(g_A + (size_t)row * DD);
        ndst = g_nA + row;
        if (threadIdx.x == 0) g_min[row] = 0x7F800000u;  // +inf
    } else {
        int r = row - MM;
        src = (const float4*)(cents + (size_t)r * DD);
        dst = (uint2*)(g_Bc + (size_t)r * DD);
        ndst = g_nB + r;
    }
    float s = 0.f;
#pragma unroll
    for (int i = 0; i < DD / 4 / PT; ++i) {
        int j = i * PT + threadIdx.x;
        float4 v = src[j];
        __half2 lo = __floats2half2_rn(v.x, v.y);
        __half2 hi = __floats2half2_rn(v.z, v.w);
        uint2 pk;
        pk.x = *(uint32_t*)&lo;
        pk.y = *(uint32_t*)&hi;
        dst[j] = pk;
        s += v.x * v.x + v.y * v.y + v.z * v.z + v.w * v.w;
    }
#pragma unroll
    for (int off = 16; off; off >>= 1)
        s += __shfl_xor_sync(0xffffffffu, s, off);
    __shared__ float ws[PT / 32];
    int lane = threadIdx.x & 31, warp = threadIdx.x >> 5;
    if (lane == 0) ws[warp] = s;
    __syncthreads();
    if (threadIdx.x == 0) {
        float t = 0.f;
#pragma unroll
        for (int w = 0; w < PT / 32; ++w) t += ws[w];
        *ndst = t;
    }
    if (row == 0 && threadIdx.x < loss_elems) out[threadIdx.x] = 0.f;
}

// ---------------------------------------------------------------------------
// PTX helpers (generic ISA only)
// ---------------------------------------------------------------------------
__device__ __forceinline__ uint32_t smem_u32(const void* p) {
    return (uint32_t)__cvta_generic_to_shared(p);
}
__device__ __forceinline__ void cp16(void* s, const void* g) {
    asm volatile("cp.async.cg.shared.global [%0], [%1], 16;\n"
                 :: "r"(smem_u32(s)), "l"(g));
}
__device__ __forceinline__ void cp_commit() {
    asm volatile("cp.async.commit_group;\n");
}
template <int N>
__device__ __forceinline__ void cp_wait() {
    asm volatile("cp.async.wait_group %0;\n" :: "n"(N));
}
__device__ __forceinline__ void ldm_x4(uint32_t* r, const __half* p) {
    asm volatile("ldmatrix.sync.aligned.m8n8.x4.shared.b16 {%0,%1,%2,%3}, [%4];\n"
                 : "=r"(r[0]), "=r"(r[1]), "=r"(r[2]), "=r"(r[3])
                 : "r"(smem_u32(p)));
}
__device__ __forceinline__ void mma_f16(uint32_t* c, const uint32_t* a,
                                        const uint32_t* b) {
    asm volatile("mma.sync.aligned.m16n8k16.row.col.f16.f16.f16.f16 "
                 "{%0,%1}, {%2,%3,%4,%5}, {%6,%7}, {%0,%1};\n"
                 : "+r"(c[0]), "+r"(c[1])
                 : "r"(a[0]), "r"(a[1]), "r"(a[2]), "r"(a[3]),
                   "r"(b[0]), "r"(b[1]));
}
// XOR-swizzled half offset for (row, 16B-chunk c8) in a [rows][64]-half tile.
__device__ __forceinline__ int swz(int row, int c8) {
    return row * 64 + ((c8 ^ (row & 7)) << 3);
}

// ---------------------------------------------------------------------------
// Persistent HMMA(f16-acc) GEMM-min: 256x256 CTA tile, 16 warps (4x4),
// 64x64 warp tiles, 3-stage cp.async ring, 1 CTA/SM.
// ---------------------------------------------------------------------------
struct SmemTile { __half a[BM * 64]; __half b[BN * 64]; };

__device__ __forceinline__ void issue_stage(SmemTile* st, int m0, int p0, int kc,
                                            int tid) {
    const __half* Ag = g_A + (size_t)m0 * DD + kc * BK;
    const __half* Bg = g_Bc + (size_t)p0 * DD + kc * BK;
    // A: 2048 16B-chunks, B: 2048 -> 8 iterations of 512 threads
#pragma unroll
    for (int t = 0; t < 4; ++t) {
        int idx = tid + t * THREADS;
        int row = idx >> 3, c8 = idx & 7;
        cp16(st->a + swz(row, c8), Ag + (size_t)row * DD + c8 * 8);
    }
#pragma unroll
    for (int t = 0; t < 4; ++t) {
        int idx = tid + t * THREADS;
        int row = idx >> 3, c8 = idx & 7;
        cp16(st->b + swz(row, c8), Bg + (size_t)row * DD + c8 * 8);
    }
}

__global__ __launch_bounds__(THREADS, 1)
void gemm_min_kernel() {
    extern __shared__ __align__(16) char smem_raw[];
    SmemTile* stages = (SmemTile*)smem_raw;

    const int tid = threadIdx.x;
    const int lane = tid & 31, warp = tid >> 5;
    const int wm = warp >> 2, wn = warp & 3;          // 4(M) x 4(N) warp grid

    const int arow  = (lane & 7) + ((lane >> 3) & 1) * 8;
    const int acbit = (lane >> 4) & 1;

    for (int it = blockIdx.x; it < NITEMS; it += GRID) {
        const int m0 = (it >> 4) * BM;        // 98 m-tiles
        const int p0 = (it & 15) * BN;        // 16 n-tiles

        uint32_t acc[4][8][2];                // f16x2 accumulators (64 regs)
#pragma unroll
        for (int i = 0; i < 4; ++i)
#pragma unroll
            for (int j = 0; j < 8; ++j) { acc[i][j][0] = 0u; acc[i][j][1] = 0u; }

        issue_stage(&stages[0], m0, p0, 0, tid);
        cp_commit();
        issue_stage(&stages[1], m0, p0, 1, tid);
        cp_commit();

#pragma unroll 1
        for (int kc = 0; kc < NKC; ++kc) {
            cp_wait<1>();
            __syncthreads();
            if (kc + 2 < NKC)
                issue_stage(&stages[(kc + 2) % NSTAGE], m0, p0, kc + 2, tid);
            cp_commit();

            const SmemTile* st = &stages[kc % NSTAGE];
#pragma unroll
            for (int ks = 0; ks < BK / 16; ++ks) {
                int c8 = ks * 2 + acbit;
                uint32_t a[4][4];
#pragma unroll
                for (int mt = 0; mt < 4; ++mt) {
                    int row = wm * 64 + mt * 16 + arow;
                    ldm_x4(a[mt], st->a + swz(row, c8));
                }
                uint32_t b[8][2];
#pragma unroll
                for (int tp = 0; tp < 4; ++tp) {
                    uint32_t r[4];
                    int row = wn * 64 + tp * 16 + arow;
                    ldm_x4(r, st->b + swz(row, c8));
                    b[2 * tp][0] = r[0];  b[2 * tp][1] = r[2];
                    b[2 * tp + 1][0] = r[1]; b[2 * tp + 1][1] = r[3];
                }
#pragma unroll
                for (int mt = 0; mt < 4; ++mt)
#pragma unroll
                    for (int j = 0; j < 8; ++j)
                        mma_f16(acc[mt][j], a[mt], b[j]);
            }
        }
        __syncthreads();   // last stage consumed before next item reuses ring

        // epilogue: unpack f16x2, min over warp's 64 cols, fold, atomicMin
        float rmin[4][2];
#pragma unroll
        for (int mt = 0; mt < 4; ++mt) { rmin[mt][0] = 3.4e38f; rmin[mt][1] = 3.4e38f; }
#pragma unroll
        for (int j = 0; j < 8; ++j) {
            int col = p0 + wn * 64 + j * 8 + (lane & 3) * 2;
            float nc0 = g_nB[col], nc1 = g_nB[col + 1];
#pragma unroll
            for (int mt = 0; mt < 4; ++mt) {
                float2 lo = __half22float2(*(__half2*)&acc[mt][j][0]); // row r
                float2 hi = __half22float2(*(__half2*)&acc[mt][j][1]); // row r+8
                float v0 = fminf(nc0 - 2.f * lo.x, nc1 - 2.f * lo.y);
                float v1 = fminf(nc0 - 2.f * hi.x, nc1 - 2.f * hi.y);
                rmin[mt][0] = fminf(rmin[mt][0], v0);
                rmin[mt][1] = fminf(rmin[mt][1], v1);
            }
        }
#pragma unroll
        for (int mt = 0; mt < 4; ++mt)
#pragma unroll
            for (int h = 0; h < 2; ++h) {
                float v = rmin[mt][h];
                v = fminf(v, __shfl_xor_sync(0xffffffffu, v, 1));
                v = fminf(v, __shfl_xor_sync(0xffffffffu, v, 2));
                rmin[mt][h] = v;
            }
        if ((lane & 3) == 0) {
            int q = lane >> 2;
#pragma unroll
            for (int mt = 0; mt < 4; ++mt)
#pragma unroll
                for (int h = 0; h < 2; ++h) {
                    int m = m0 + wm * 64 + mt * 16 + h * 8 + q;
                    float d2 = fmaxf(g_nA[m] + rmin[mt][h], 0.f);
                    atomicMin(&g_min[m], __float_as_uint(d2));
                }
        }
    }
}

// ---------------------------------------------------------------------------
// Final: sqrt of the folded min distance^2.
// ---------------------------------------------------------------------------
__global__ void sqrt_kernel(float* __restrict__ out, int offset) {
    int m = blockIdx.x * blockDim.x + threadIdx.x;
    if (m < MM) out[offset + m] = sqrtf(__uint_as_float(g_min[m]));
}

// ---------------------------------------------------------------------------
extern "C" void kernel_launch(void* const* d_in, const int* in_sizes, int n_in,
                              void* d_out, int out_size) {
    const float* embeds = (const float*)d_in[0];
    const float* cents  = (const float*)d_in[1];
    if (n_in >= 2 && in_sizes[0] == PP * DD && in_sizes[1] == MM * DD) {
        embeds = (const float*)d_in[1];
        cents  = (const float*)d_in[0];
    }
    float* out = (float*)d_out;
    int loss_elems = out_size - MM;
    if (loss_elems < 0) loss_elems = 0;

    cudaFuncSetAttribute(gemm_min_kernel,
                         cudaFuncAttributeMaxDynamicSharedMemorySize, SMEM_BYTES);

    prep_kernel<<<MM + PP, PT>>>(embeds, cents, out, loss_elems);
    gemm_min_kernel<<<GRID, THREADS, SMEM_BYTES>>>();
    sqrt_kernel<<<(MM + 255) / 256, 256>>>(out, loss_elems);
}

// round 10
// speedup vs baseline: 1.0014x; 1.0014x over previous
#include <cuda_runtime.h>
#include <cuda_fp16.h>
#include <stdint.h>

// ---------------- Problem shape ----------------
#define BB 8
#define NN 3136
#define DD 1536
#define PP 4096
#define MM (BB*NN)          // 25088

// ---------------- Tiling ----------------
#define BM 128
#define BN 128
#define BK 64               // fp16 per k-chunk (128 B rows)
#define NKC (DD/BK)         // 24
#define NMT (MM/BM)         // 196
#define NNT (PP/BN)         // 32
#define NITEMS (NMT*NNT)    // 6272
#define GRID 296            // 2 persistent CTAs per SM
#define THREADS 256
#define NSTAGE 3

#define STAGE_BYTES ((BM+BN)*BK*2)           // 32768
#define SMEM_BYTES (NSTAGE*STAGE_BYTES)      // 98304 (2 CTAs/SM -> 192KB/SM)

// ---------------- Scratch (device globals: allocation-free rule) ------------
__device__ __half g_A[(size_t)MM*DD];          // embeds f16
__device__ __half g_Bc[(size_t)PP*DD];         // centroids f16
__device__ float g_nA[MM];                     // ||x||^2 (fp32 from fp32 inputs)
__device__ float g_nB[PP];                     // ||c||^2
__device__ unsigned int g_min[MM];             // running min of dist^2 (uint bits)

// ---------------------------------------------------------------------------
// Prep: fp32 -> fp16 (vectorized) + fp32 squared norms + g_min init.
// ---------------------------------------------------------------------------
#define PT 128
__global__ void prep_kernel(const float* __restrict__ embeds,
                            const float* __restrict__ cents,
                            float* __restrict__ out, int loss_elems) {
    int row = blockIdx.x;
    const float4* src;
    uint2* dst;
    float* ndst;
    if (row < MM) {
        src = (const float4*)(embeds + (size_t)row * DD);
        dst = (uint2*)(g_A + (size_t)row * DD);
        ndst = g_nA + row;
        if (threadIdx.x == 0) g_min[row] = 0x7F800000u;  // +inf
    } else {
        int r = row - MM;
        src = (const float4*)(cents + (size_t)r * DD);
        dst = (uint2*)(g_Bc + (size_t)r * DD);
        ndst = g_nB + r;
    }
    float s = 0.f;
#pragma unroll
    for (int i = 0; i < DD / 4 / PT; ++i) {
        int j = i * PT + threadIdx.x;
        float4 v = src[j];
        __half2 lo = __floats2half2_rn(v.x, v.y);
        __half2 hi = __floats2half2_rn(v.z, v.w);
        uint2 pk;
        pk.x = *(uint32_t*)&lo;
        pk.y = *(uint32_t*)&hi;
        dst[j] = pk;
        s += v.x * v.x + v.y * v.y + v.z * v.z + v.w * v.w;
    }
#pragma unroll
    for (int off = 16; off; off >>= 1)
        s += __shfl_xor_sync(0xffffffffu, s, off);
    __shared__ float ws[PT / 32];
    int lane = threadIdx.x & 31, warp = threadIdx.x >> 5;
    if (lane == 0) ws[warp] = s;
    __syncthreads();
    if (threadIdx.x == 0) {
        float t = 0.f;
#pragma unroll
        for (int w = 0; w < PT / 32; ++w) t += ws[w];
        *ndst = t;
    }
    if (row == 0 && threadIdx.x < loss_elems) out[threadIdx.x] = 0.f;
}

// ---------------------------------------------------------------------------
// PTX helpers (generic ISA only)
// ---------------------------------------------------------------------------
__device__ __forceinline__ uint32_t smem_u32(const void* p) {
    return (uint32_t)__cvta_generic_to_shared(p);
}
__device__ __forceinline__ void cp16(void* s, const void* g) {
    asm volatile("cp.async.cg.shared.global [%0], [%1], 16;\n"
                 :: "r"(smem_u32(s)), "l"(g));
}
__device__ __forceinline__ void cp_commit() {
    asm volatile("cp.async.commit_group;\n");
}
template <int N>
__device__ __forceinline__ void cp_wait() {
    asm volatile("cp.async.wait_group %0;\n" :: "n"(N));
}
__device__ __forceinline__ void ldm_x4(uint32_t* r, const __half* p) {
    asm volatile("ldmatrix.sync.aligned.m8n8.x4.shared.b16 {%0,%1,%2,%3}, [%4];\n"
                 : "=r"(r[0]), "=r"(r[1]), "=r"(r[2]), "=r"(r[3])
                 : "r"(smem_u32(p)));
}
__device__ __forceinline__ void mma_f16(uint32_t* c, const uint32_t* a,
                                        const uint32_t* b) {
    asm volatile("mma.sync.aligned.m16n8k16.row.col.f16.f16.f16.f16 "
                 "{%0,%1}, {%2,%3,%4,%5}, {%6,%7}, {%0,%1};\n"
                 : "+r"(c[0]), "+r"(c[1])
                 : "r"(a[0]), "r"(a[1]), "r"(a[2]), "r"(a[3]),
                   "r"(b[0]), "r"(b[1]));
}
// XOR-swizzled half offset for (row, 16B-chunk c8) in a [rows][64]-half tile.
__device__ __forceinline__ int swz(int row, int c8) {
    return row * 64 + ((c8 ^ (row & 7)) << 3);
}

// ---------------------------------------------------------------------------
// Persistent HMMA(f16-acc) GEMM-min with a CONTINUOUS cross-item pipeline:
// one flat chunk stream per CTA, 3-slot ring, prefetch distance 2 — the
// cp.async pipeline never drains across item boundaries.
// ---------------------------------------------------------------------------
struct SmemTile { __half a[BM * 64]; __half b[BN * 64]; };

__device__ __forceinline__ void issue_stage(SmemTile* st, int item, int kc,
                                            int tid) {
    const int m0 = (item >> 5) * BM;
    const int p0 = (item & 31) * BN;
    const __half* Ag = g_A + (size_t)m0 * DD + kc * BK;
    const __half* Bg = g_Bc + (size_t)p0 * DD + kc * BK;
#pragma unroll
    for (int t = 0; t < 4; ++t) {
        int idx = tid + t * THREADS;
        int row = idx >> 3, c8 = idx & 7;
        cp16(st->a + swz(row, c8), Ag + (size_t)row * DD + c8 * 8);
        cp16(st->b + swz(row, c8), Bg + (size_t)row * DD + c8 * 8);
    }
}

__device__ __forceinline__ void load_frags(uint32_t a[2][4], uint32_t b[8][2],
                                           const SmemTile* st, int ks,
                                           int wm, int wn, int arow, int acbit) {
    int c8 = ks * 2 + acbit;
#pragma unroll
    for (int mt = 0; mt < 2; ++mt) {
        int row = wm * 32 + mt * 16 + arow;
        ldm_x4(a[mt], st->a + swz(row, c8));
    }
#pragma unroll
    for (int tp = 0; tp < 4; ++tp) {
        uint32_t r[4];
        int row = wn * 64 + tp * 16 + arow;
        ldm_x4(r, st->b + swz(row, c8));
        b[2 * tp][0] = r[0];  b[2 * tp][1] = r[2];
        b[2 * tp + 1][0] = r[1]; b[2 * tp + 1][1] = r[3];
    }
}

__global__ __launch_bounds__(THREADS, 2)
void gemm_min_kernel() {
    extern __shared__ __align__(16) char smem_raw[];
    SmemTile* stages = (SmemTile*)smem_raw;

    const int tid = threadIdx.x;
    const int lane = tid & 31, warp = tid >> 5;
    const int wm = warp >> 1, wn = warp & 1;          // 4(M) x 2(N) warps

    const int arow  = (lane & 7) + ((lane >> 3) & 1) * 8;
    const int acbit = (lane >> 4) & 1;

    // prefetch pointer (flat chunk stream), 2 chunks ahead of compute
    int pf_item = blockIdx.x, pf_kc = 0;
    int pf_slot = 0;
    issue_stage(&stages[0], pf_item, 0, tid);  cp_commit();
    issue_stage(&stages[1], pf_item, 1, tid);  cp_commit();
    pf_kc = 2;  pf_slot = 2;

    int slot = 0;   // ring slot of the chunk being computed

    for (int it = blockIdx.x; it < NITEMS; it += GRID) {
        const int m0 = (it >> 5) * BM;
        const int p0 = (it & 31) * BN;

        uint32_t acc[2][8][2];                        // f16x2 accumulators
#pragma unroll
        for (int i = 0; i < 2; ++i)
#pragma unroll
            for (int j = 0; j < 8; ++j) { acc[i][j][0] = 0u; acc[i][j][1] = 0u; }

#pragma unroll 1
        for (int kc = 0; kc < NKC; ++kc) {
            cp_wait<1>();          // compute chunk arrived
            __syncthreads();       // visible to all; slot being refilled is free
            if (pf_item < NITEMS)
                issue_stage(&stages[pf_slot], pf_item, pf_kc, tid);
            cp_commit();
            pf_slot = (pf_slot + 1 < NSTAGE) ? pf_slot + 1 : 0;
            if (++pf_kc == NKC) { pf_kc = 0; pf_item += GRID; }

            const SmemTile* st = &stages[slot];
            slot = (slot + 1 < NSTAGE) ? slot + 1 : 0;

            // register double-buffered fragments over 4 k-steps
            uint32_t a[2][2][4], b[2][8][2];
            load_frags(a[0], b[0], st, 0, wm, wn, arow, acbit);
#pragma unroll
            for (int ks = 0; ks < BK / 16; ++ks) {
                int cur = ks & 1;
                if (ks + 1 < BK / 16)
                    load_frags(a[cur ^ 1], b[cur ^ 1], st, ks + 1,
                               wm, wn, arow, acbit);
#pragma unroll
                for (int mt = 0; mt < 2; ++mt)
#pragma unroll
                    for (int j = 0; j < 8; ++j)
                        mma_f16(acc[mt][j], a[cur][mt], b[cur][j]);
            }
        }

        // epilogue (next item's chunks already loading underneath)
        float rmin[2][2] = {{3.4e38f, 3.4e38f}, {3.4e38f, 3.4e38f}};
#pragma unroll
        for (int j = 0; j < 8; ++j) {
            int col = p0 + wn * 64 + j * 8 + (lane & 3) * 2;
            float nc0 = g_nB[col], nc1 = g_nB[col + 1];
#pragma unroll
            for (int mt = 0; mt < 2; ++mt) {
                float2 lo = __half22float2(*(__half2*)&acc[mt][j][0]); // row r
                float2 hi = __half22float2(*(__half2*)&acc[mt][j][1]); // row r+8
                float v0 = fminf(nc0 - 2.f * lo.x, nc1 - 2.f * lo.y);
                float v1 = fminf(nc0 - 2.f * hi.x, nc1 - 2.f * hi.y);
                rmin[mt][0] = fminf(rmin[mt][0], v0);
                rmin[mt][1] = fminf(rmin[mt][1], v1);
            }
        }
#pragma unroll
        for (int mt = 0; mt < 2; ++mt)
#pragma unroll
            for (int h = 0; h < 2; ++h) {
                float v = rmin[mt][h];
                v = fminf(v, __shfl_xor_sync(0xffffffffu, v, 1));
                v = fminf(v, __shfl_xor_sync(0xffffffffu, v, 2));
                rmin[mt][h] = v;
            }
        if ((lane & 3) == 0) {
            int q = lane >> 2;
#pragma unroll
            for (int mt = 0; mt < 2; ++mt)
#pragma unroll
                for (int h = 0; h < 2; ++h) {
                    int m = m0 + wm * 32 + mt * 16 + h * 8 + q;
                    float d2 = fmaxf(g_nA[m] + rmin[mt][h], 0.f);
                    atomicMin(&g_min[m], __float_as_uint(d2));
                }
        }
    }
}

// ---------------------------------------------------------------------------
// Final: sqrt of the folded min distance^2.
// ---------------------------------------------------------------------------
__global__ void sqrt_kernel(float* __restrict__ out, int offset) {
    int m = blockIdx.x * blockDim.x + threadIdx.x;
    if (m < MM) out[offset + m] = sqrtf(__uint_as_float(g_min[m]));
}

// ---------------------------------------------------------------------------
extern "C" void kernel_launch(void* const* d_in, const int* in_sizes, int n_in,
                              void* d_out, int out_size) {
    const float* embeds = (const float*)d_in[0];
    const float* cents  = (const float*)d_in[1];
    if (n_in >= 2 && in_sizes[0] == PP * DD && in_sizes[1] == MM * DD) {
        embeds = (const float*)d_in[1];
        cents  = (const float*)d_in[0];
    }
    float* out = (float*)d_out;
    int loss_elems = out_size - MM;
    if (loss_elems < 0) loss_elems = 0;

    cudaFuncSetAttribute(gemm_min_kernel,
                         cudaFuncAttributeMaxDynamicSharedMemorySize, SMEM_BYTES);

    prep_kernel<<<MM + PP, PT>>>(embeds, cents, out, loss_elems);
    gemm_min_kernel<<<GRID, THREADS, SMEM_BYTES>>>();
    sqrt_kernel<<<(MM + 255) / 256, 256>>>(out, loss_elems);
}

// round 11
// speedup vs baseline: 1.0432x; 1.0417x over previous
#include <cuda_runtime.h>
#include <cuda_fp16.h>
#include <stdint.h>

// ---------------- Problem shape ----------------
#define BB 8
#define NN 3136
#define DD 1536
#define PP 4096
#define MM (BB*NN)          // 25088

// ---------------- Tiling ----------------
#define BM 128
#define BN 128
#define BK 64               // fp16 per k-chunk (128 B rows)
#define NKC (DD/BK)         // 24
#define NMT (MM/BM)         // 196
#define NNT (PP/BN)         // 32
#define NITEMS (NMT*NNT)    // 6272
#define GRID 444            // 3 persistent CTAs per SM
#define THREADS 256

#define SMEM_BYTES (2*BM*64*2 + 2*BN*64*2)   // 65536 (2-stage A+B) -> 192KB/SM

// ---------------- Scratch (device globals: allocation-free rule) ------------
__device__ __half g_A[(size_t)MM*DD];          // embeds f16
__device__ __half g_Bc[(size_t)PP*DD];         // centroids f16
__device__ float g_nA[MM];                     // ||x||^2 (fp32 from fp32 inputs)
__device__ float g_nB[PP];                     // ||c||^2
__device__ unsigned int g_min[MM];             // running min of dist^2 (uint bits)

// ---------------------------------------------------------------------------
// Prep: fp32 -> fp16 (vectorized) + fp32 squared norms + g_min init.
// ---------------------------------------------------------------------------
#define PT 128
__global__ void prep_kernel(const float* __restrict__ embeds,
                            const float* __restrict__ cents,
                            float* __restrict__ out, int loss_elems) {
    int row = blockIdx.x;
    const float4* src;
    uint2* dst;
    float* ndst;
    if (row < MM) {
        src = (const float4*)(embeds + (size_t)row * DD);
        dst = (uint2*)(g_A + (size_t)row * DD);
        ndst = g_nA + row;
        if (threadIdx.x == 0) g_min[row] = 0x7F800000u;  // +inf
    } else {
        int r = row - MM;
        src = (const float4*)(cents + (size_t)r * DD);
        dst = (uint2*)(g_Bc + (size_t)r * DD);
        ndst = g_nB + r;
    }
    float s = 0.f;
#pragma unroll
    for (int i = 0; i < DD / 4 / PT; ++i) {
        int j = i * PT + threadIdx.x;
        float4 v = src[j];
        __half2 lo = __floats2half2_rn(v.x, v.y);
        __half2 hi = __floats2half2_rn(v.z, v.w);
        uint2 pk;
        pk.x = *(uint32_t*)&lo;
        pk.y = *(uint32_t*)&hi;
        dst[j] = pk;
        s += v.x * v.x + v.y * v.y + v.z * v.z + v.w * v.w;
    }
#pragma unroll
    for (int off = 16; off; off >>= 1)
        s += __shfl_xor_sync(0xffffffffu, s, off);
    __shared__ float ws[PT / 32];
    int lane = threadIdx.x & 31, warp = threadIdx.x >> 5;
    if (lane == 0) ws[warp] = s;
    __syncthreads();
    if (threadIdx.x == 0) {
        float t = 0.f;
#pragma unroll
        for (int w = 0; w < PT / 32; ++w) t += ws[w];
        *ndst = t;
    }
    if (row == 0 && threadIdx.x < loss_elems) out[threadIdx.x] = 0.f;
}

// ---------------------------------------------------------------------------
// PTX helpers (generic ISA only)
// ---------------------------------------------------------------------------
__device__ __forceinline__ uint32_t smem_u32(const void* p) {
    return (uint32_t)__cvta_generic_to_shared(p);
}
__device__ __forceinline__ void cp16(void* s, const void* g) {
    asm volatile("cp.async.cg.shared.global [%0], [%1], 16;\n"
                 :: "r"(smem_u32(s)), "l"(g));
}
__device__ __forceinline__ void cp_commit() {
    asm volatile("cp.async.commit_group;\n");
}
template <int N>
__device__ __forceinline__ void cp_wait() {
    asm volatile("cp.async.wait_group %0;\n" :: "n"(N));
}
__device__ __forceinline__ void ldm_x4(uint32_t* r, const __half* p) {
    asm volatile("ldmatrix.sync.aligned.m8n8.x4.shared.b16 {%0,%1,%2,%3}, [%4];\n"
                 : "=r"(r[0]), "=r"(r[1]), "=r"(r[2]), "=r"(r[3])
                 : "r"(smem_u32(p)));
}
__device__ __forceinline__ void mma_f16(uint32_t* c, const uint32_t* a,
                                        const uint32_t* b) {
    asm volatile("mma.sync.aligned.m16n8k16.row.col.f16.f16.f16.f16 "
                 "{%0,%1}, {%2,%3,%4,%5}, {%6,%7}, {%0,%1};\n"
                 : "+r"(c[0]), "+r"(c[1])
                 : "r"(a[0]), "r"(a[1]), "r"(a[2]), "r"(a[3]),
                   "r"(b[0]), "r"(b[1]));
}
// XOR-swizzled half offset for (row, 16B-chunk c8) in a [rows][64]-half tile.
__device__ __forceinline__ int swz(int row, int c8) {
    return row * 64 + ((c8 ^ (row & 7)) << 3);
}

// ---------------------------------------------------------------------------
// Persistent HMMA(f16-acc) GEMM-min. 444 CTAs, 3/SM, 6272 items.
// Item = (m-tile 128) x (n-tile 128), full K, fold min via atomicMin.
// ---------------------------------------------------------------------------
__global__ __launch_bounds__(THREADS, 3)
void gemm_min_kernel() {
    extern __shared__ __align__(16) char smem_raw[];
    __half* As = (__half*)smem_raw;                   // 2 x [128][64]
    __half* Bs = As + 2 * BM * 64;                    // 2 x [128][64]

    const int tid = threadIdx.x;
    const int lane = tid & 31, warp = tid >> 5;
    const int wm = warp >> 1, wn = warp & 1;          // 4(M) x 2(N) warps

    const int arow  = (lane & 7) + ((lane >> 3) & 1) * 8;
    const int acbit = (lane >> 4) & 1;

    for (int it = blockIdx.x; it < NITEMS; it += GRID) {
        const int m0 = (it >> 5) * BM;
        const int p0 = (it & 31) * BN;

        uint32_t acc[2][8][2];                        // f16x2 accumulators
#pragma unroll
        for (int i = 0; i < 2; ++i)
#pragma unroll
            for (int j = 0; j < 8; ++j) { acc[i][j][0] = 0u; acc[i][j][1] = 0u; }

        // prologue: chunk 0 -> buffer 0
        {
            const __half* Ag = g_A + (size_t)m0 * DD;
            const __half* Bg = g_Bc + (size_t)p0 * DD;
#pragma unroll
            for (int t = 0; t < 4; ++t) {
                int idx = tid + t * THREADS;
                int row = idx >> 3, c8 = idx & 7;
                cp16(As + swz(row, c8), Ag + (size_t)row * DD + c8 * 8);
                cp16(Bs + swz(row, c8), Bg + (size_t)row * DD + c8 * 8);
            }
            cp_commit();
        }

#pragma unroll 1
        for (int kc = 0; kc < NKC; ++kc) {
            if (kc + 1 < NKC) {
                int buf = (kc + 1) & 1;
                const __half* Ag = g_A + (size_t)m0 * DD + (kc + 1) * BK;
                const __half* Bg = g_Bc + (size_t)p0 * DD + (kc + 1) * BK;
                __half* Asb = As + buf * BM * 64;
                __half* Bsb = Bs + buf * BN * 64;
#pragma unroll
                for (int t = 0; t < 4; ++t) {
                    int idx = tid + t * THREADS;
                    int row = idx >> 3, c8 = idx & 7;
                    cp16(Asb + swz(row, c8), Ag + (size_t)row * DD + c8 * 8);
                    cp16(Bsb + swz(row, c8), Bg + (size_t)row * DD + c8 * 8);
                }
                cp_commit();
                cp_wait<1>();
            } else {
                cp_wait<0>();
            }
            __syncthreads();

            const __half* Asb = As + (kc & 1) * BM * 64;
            const __half* Bsb = Bs + (kc & 1) * BN * 64;
#pragma unroll
            for (int ks = 0; ks < BK / 16; ++ks) {
                uint32_t a[2][4];
                int c8 = ks * 2 + acbit;
#pragma unroll
                for (int mt = 0; mt < 2; ++mt) {
                    int row = wm * 32 + mt * 16 + arow;
                    ldm_x4(a[mt], Asb + swz(row, c8));
                }
                uint32_t b[8][2];
#pragma unroll
                for (int tp = 0; tp < 4; ++tp) {
                    uint32_t r[4];
                    int row = wn * 64 + tp * 16 + arow;
                    ldm_x4(r, Bsb + swz(row, c8));
                    b[2 * tp][0] = r[0];  b[2 * tp][1] = r[2];
                    b[2 * tp + 1][0] = r[1]; b[2 * tp + 1][1] = r[3];
                }
#pragma unroll
                for (int mt = 0; mt < 2; ++mt)
#pragma unroll
                    for (int j = 0; j < 8; ++j)
                        mma_f16(acc[mt][j], a[mt], b[j]);
            }
            __syncthreads();
        }

        // epilogue: unpack f16x2 accs, min over warp's 64 cols, atomicMin
        float rmin[2][2] = {{3.4e38f, 3.4e38f}, {3.4e38f, 3.4e38f}};
#pragma unroll
        for (int j = 0; j < 8; ++j) {
            int col = p0 + wn * 64 + j * 8 + (lane & 3) * 2;
            float nc0 = g_nB[col], nc1 = g_nB[col + 1];
#pragma unroll
            for (int mt = 0; mt < 2; ++mt) {
                float2 lo = __half22float2(*(__half2*)&acc[mt][j][0]); // row r
                float2 hi = __half22float2(*(__half2*)&acc[mt][j][1]); // row r+8
                float v0 = fminf(nc0 - 2.f * lo.x, nc1 - 2.f * lo.y);
                float v1 = fminf(nc0 - 2.f * hi.x, nc1 - 2.f * hi.y);
                rmin[mt][0] = fminf(rmin[mt][0], v0);
                rmin[mt][1] = fminf(rmin[mt][1], v1);
            }
        }
#pragma unroll
        for (int mt = 0; mt < 2; ++mt)
#pragma unroll
            for (int h = 0; h < 2; ++h) {
                float v = rmin[mt][h];
                v = fminf(v, __shfl_xor_sync(0xffffffffu, v, 1));
                v = fminf(v, __shfl_xor_sync(0xffffffffu, v, 2));
                rmin[mt][h] = v;
            }
        if ((lane & 3) == 0) {
            int q = lane >> 2;
#pragma unroll
            for (int mt = 0; mt < 2; ++mt)
#pragma unroll
                for (int h = 0; h < 2; ++h) {
                    int m = m0 + wm * 32 + mt * 16 + h * 8 + q;
                    float d2 = fmaxf(g_nA[m] + rmin[mt][h], 0.f);
                    atomicMin(&g_min[m], __float_as_uint(d2));
                }
        }
    }
}

// ---------------------------------------------------------------------------
// Final: sqrt of the folded min distance^2.
// ---------------------------------------------------------------------------
__global__ void sqrt_kernel(float* __restrict__ out, int offset) {
    int m = blockIdx.x * blockDim.x + threadIdx.x;
    if (m < MM) out[offset + m] = sqrtf(__uint_as_float(g_min[m]));
}

// ---------------------------------------------------------------------------
extern "C" void kernel_launch(void* const* d_in, const int* in_sizes, int n_in,
                              void* d_out, int out_size) {
    const float* embeds = (const float*)d_in[0];
    const float* cents  = (const float*)d_in[1];
    if (n_in >= 2 && in_sizes[0] == PP * DD && in_sizes[1] == MM * DD) {
        embeds = (const float*)d_in[1];
        cents  = (const float*)d_in[0];
    }
    float* out = (float*)d_out;
    int loss_elems = out_size - MM;
    if (loss_elems < 0) loss_elems = 0;

    cudaFuncSetAttribute(gemm_min_kernel,
                         cudaFuncAttributeMaxDynamicSharedMemorySize, SMEM_BYTES);

    prep_kernel<<<MM + PP, PT>>>(embeds, cents, out, loss_elems);
    gemm_min_kernel<<<GRID, THREADS, SMEM_BYTES>>>();
    sqrt_kernel<<<(MM + 255) / 256, 256>>>(out, loss_elems);
}

// round 12
// speedup vs baseline: 1.0515x; 1.0080x over previous
#include <cuda_runtime.h>
#include <cuda_fp16.h>
#include <stdint.h>

// ---------------- Problem shape ----------------
#define BB 8
#define NN 3136
#define DD 1536
#define PP 4096
#define MM (BB*NN)          // 25088

// ---------------- Tiling ----------------
#define BM 128
#define BN 128
#define BK 64               // fp16 per k-chunk (128 B rows)
#define NKC (DD/BK)         // 24
#define NMT (MM/BM)         // 196
#define NNT (PP/BN)         // 32
#define NITEMS (NMT*NNT)    // 6272
#define GRID 444            // 3 persistent CTAs per SM
#define THREADS 256

#define SMEM_BYTES (2*BM*64*2 + 2*BN*64*2)   // 65536 (2-stage A+B) -> 192KB/SM

// ---------------- Scratch (device globals: allocation-free rule) ------------
__device__ __half g_A[(size_t)MM*DD];          // embeds f16
__device__ __half g_Bc[(size_t)PP*DD];         // centroids f16
__device__ float g_nA[MM];                     // ||x||^2 (fp32 from fp32 inputs)
__device__ float g_nB[PP];                     // ||c||^2
__device__ unsigned int g_min[MM];             // running min of dist^2 (uint bits)

// ---------------------------------------------------------------------------
// Prep: fp32 -> fp16 (vectorized) + fp32 squared norms + g_min init.
// ---------------------------------------------------------------------------
#define PT 128
__global__ void prep_kernel(const float* __restrict__ embeds,
                            const float* __restrict__ cents,
                            float* __restrict__ out, int loss_elems) {
    int row = blockIdx.x;
    const float4* src;
    uint2* dst;
    float* ndst;
    if (row < MM) {
        src = (const float4*)(embeds + (size_t)row * DD);
        dst = (uint2*)(g_A + (size_t)row * DD);
        ndst = g_nA + row;
        if (threadIdx.x == 0) g_min[row] = 0x7F800000u;  // +inf
    } else {
        int r = row - MM;
        src = (const float4*)(cents + (size_t)r * DD);
        dst = (uint2*)(g_Bc + (size_t)r * DD);
        ndst = g_nB + r;
    }
    float s = 0.f;
#pragma unroll
    for (int i = 0; i < DD / 4 / PT; ++i) {
        int j = i * PT + threadIdx.x;
        float4 v = src[j];
        __half2 lo = __floats2half2_rn(v.x, v.y);
        __half2 hi = __floats2half2_rn(v.z, v.w);
        uint2 pk;
        pk.x = *(uint32_t*)&lo;
        pk.y = *(uint32_t*)&hi;
        dst[j] = pk;
        s += v.x * v.x + v.y * v.y + v.z * v.z + v.w * v.w;
    }
#pragma unroll
    for (int off = 16; off; off >>= 1)
        s += __shfl_xor_sync(0xffffffffu, s, off);
    __shared__ float ws[PT / 32];
    int lane = threadIdx.x & 31, warp = threadIdx.x >> 5;
    if (lane == 0) ws[warp] = s;
    __syncthreads();
    if (threadIdx.x == 0) {
        float t = 0.f;
#pragma unroll
        for (int w = 0; w < PT / 32; ++w) t += ws[w];
        *ndst = t;
    }
    if (row == 0 && threadIdx.x < loss_elems) out[threadIdx.x] = 0.f;
}

// ---------------------------------------------------------------------------
// PTX helpers (generic ISA only)
// ---------------------------------------------------------------------------
__device__ __forceinline__ uint32_t smem_u32(const void* p) {
    return (uint32_t)__cvta_generic_to_shared(p);
}
__device__ __forceinline__ void cp16(void* s, const void* g) {
    asm volatile("cp.async.cg.shared.global [%0], [%1], 16;\n"
                 :: "r"(smem_u32(s)), "l"(g));
}
__device__ __forceinline__ void cp_commit() {
    asm volatile("cp.async.commit_group;\n");
}
template <int N>
__device__ __forceinline__ void cp_wait() {
    asm volatile("cp.async.wait_group %0;\n" :: "n"(N));
}
__device__ __forceinline__ void ldm_x4(uint32_t* r, const __half* p) {
    asm volatile("ldmatrix.sync.aligned.m8n8.x4.shared.b16 {%0,%1,%2,%3}, [%4];\n"
                 : "=r"(r[0]), "=r"(r[1]), "=r"(r[2]), "=r"(r[3])
                 : "r"(smem_u32(p)));
}
__device__ __forceinline__ void mma_f16(uint32_t* c, const uint32_t* a,
                                        const uint32_t* b) {
    asm volatile("mma.sync.aligned.m16n8k16.row.col.f16.f16.f16.f16 "
                 "{%0,%1}, {%2,%3,%4,%5}, {%6,%7}, {%0,%1};\n"
                 : "+r"(c[0]), "+r"(c[1])
                 : "r"(a[0]), "r"(a[1]), "r"(a[2]), "r"(a[3]),
                   "r"(b[0]), "r"(b[1]));
}
// XOR-swizzled half offset for (row, 16B-chunk c8) in a [rows][64]-half tile.
__device__ __forceinline__ int swz(int row, int c8) {
    return row * 64 + ((c8 ^ (row & 7)) << 3);
}

// ---------------------------------------------------------------------------
// Persistent HMMA(f16-acc) GEMM-min. 444 CTAs, 3/SM, 6272 items.
// SINGLE barrier per k-chunk: the top-of-chunk barrier already proves all
// warps finished reading buffer (kc-1)&1, which is the buffer the (kc+1)
// prefetch writes. Order: wait -> barrier -> prefetch -> compute.
// ---------------------------------------------------------------------------
__global__ __launch_bounds__(THREADS, 3)
void gemm_min_kernel() {
    extern __shared__ __align__(16) char smem_raw[];
    __half* As = (__half*)smem_raw;                   // 2 x [128][64]
    __half* Bs = As + 2 * BM * 64;                    // 2 x [128][64]

    const int tid = threadIdx.x;
    const int lane = tid & 31, warp = tid >> 5;
    const int wm = warp >> 1, wn = warp & 1;          // 4(M) x 2(N) warps

    const int arow  = (lane & 7) + ((lane >> 3) & 1) * 8;
    const int acbit = (lane >> 4) & 1;

    for (int it = blockIdx.x; it < NITEMS; it += GRID) {
        const int m0 = (it >> 5) * BM;
        const int p0 = (it & 31) * BN;

        uint32_t acc[2][8][2];                        // f16x2 accumulators
#pragma unroll
        for (int i = 0; i < 2; ++i)
#pragma unroll
            for (int j = 0; j < 8; ++j) { acc[i][j][0] = 0u; acc[i][j][1] = 0u; }

        // prologue: chunk 0 -> buffer 0 (safe: buf0 last read before the
        // previous item's kc=23 top barrier)
        {
            const __half* Ag = g_A + (size_t)m0 * DD;
            const __half* Bg = g_Bc + (size_t)p0 * DD;
#pragma unroll
            for (int t = 0; t < 4; ++t) {
                int idx = tid + t * THREADS;
                int row = idx >> 3, c8 = idx & 7;
                cp16(As + swz(row, c8), Ag + (size_t)row * DD + c8 * 8);
                cp16(Bs + swz(row, c8), Bg + (size_t)row * DD + c8 * 8);
            }
            cp_commit();
        }

#pragma unroll 1
        for (int kc = 0; kc < NKC; ++kc) {
            cp_wait<0>();          // chunk kc fully arrived
            __syncthreads();       // all warps done reading buffer (kc-1)&1

            if (kc + 1 < NKC) {    // prefetch kc+1 into that now-free buffer
                int buf = (kc + 1) & 1;
                const __half* Ag = g_A + (size_t)m0 * DD + (kc + 1) * BK;
                const __half* Bg = g_Bc + (size_t)p0 * DD + (kc + 1) * BK;
                __half* Asb = As + buf * BM * 64;
                __half* Bsb = Bs + buf * BN * 64;
#pragma unroll
                for (int t = 0; t < 4; ++t) {
                    int idx = tid + t * THREADS;
                    int row = idx >> 3, c8 = idx & 7;
                    cp16(Asb + swz(row, c8), Ag + (size_t)row * DD + c8 * 8);
                    cp16(Bsb + swz(row, c8), Bg + (size_t)row * DD + c8 * 8);
                }
                cp_commit();
            }

            const __half* Asb = As + (kc & 1) * BM * 64;
            const __half* Bsb = Bs + (kc & 1) * BN * 64;
#pragma unroll
            for (int ks = 0; ks < BK / 16; ++ks) {
                uint32_t a[2][4];
                int c8 = ks * 2 + acbit;
#pragma unroll
                for (int mt = 0; mt < 2; ++mt) {
                    int row = wm * 32 + mt * 16 + arow;
                    ldm_x4(a[mt], Asb + swz(row, c8));
                }
                uint32_t b[8][2];
#pragma unroll
                for (int tp = 0; tp < 4; ++tp) {
                    uint32_t r[4];
                    int row = wn * 64 + tp * 16 + arow;
                    ldm_x4(r, Bsb + swz(row, c8));
                    b[2 * tp][0] = r[0];  b[2 * tp][1] = r[2];
                    b[2 * tp + 1][0] = r[1]; b[2 * tp + 1][1] = r[3];
                }
#pragma unroll
                for (int mt = 0; mt < 2; ++mt)
#pragma unroll
                    for (int j = 0; j < 8; ++j)
                        mma_f16(acc[mt][j], a[mt], b[j]);
            }
            // no trailing barrier: next chunk's top barrier provides safety
        }

        // epilogue: unpack f16x2 accs, min over warp's 64 cols, atomicMin
        float rmin[2][2] = {{3.4e38f, 3.4e38f}, {3.4e38f, 3.4e38f}};
#pragma unroll
        for (int j = 0; j < 8; ++j) {
            int col = p0 + wn * 64 + j * 8 + (lane & 3) * 2;
            float nc0 = g_nB[col], nc1 = g_nB[col + 1];
#pragma unroll
            for (int mt = 0; mt < 2; ++mt) {
                float2 lo = __half22float2(*(__half2*)&acc[mt][j][0]); // row r
                float2 hi = __half22float2(*(__half2*)&acc[mt][j][1]); // row r+8
                float v0 = fminf(nc0 - 2.f * lo.x, nc1 - 2.f * lo.y);
                float v1 = fminf(nc0 - 2.f * hi.x, nc1 - 2.f * hi.y);
                rmin[mt][0] = fminf(rmin[mt][0], v0);
                rmin[mt][1] = fminf(rmin[mt][1], v1);
            }
        }
#pragma unroll
        for (int mt = 0; mt < 2; ++mt)
#pragma unroll
            for (int h = 0; h < 2; ++h) {
                float v = rmin[mt][h];
                v = fminf(v, __shfl_xor_sync(0xffffffffu, v, 1));
                v = fminf(v, __shfl_xor_sync(0xffffffffu, v, 2));
                rmin[mt][h] = v;
            }
        if ((lane & 3) == 0) {
            int q = lane >> 2;
#pragma unroll
            for (int mt = 0; mt < 2; ++mt)
#pragma unroll
                for (int h = 0; h < 2; ++h) {
                    int m = m0 + wm * 32 + mt * 16 + h * 8 + q;
                    float d2 = fmaxf(g_nA[m] + rmin[mt][h], 0.f);
                    atomicMin(&g_min[m], __float_as_uint(d2));
                }
        }
    }
}

// ---------------------------------------------------------------------------
// Final: sqrt of the folded min distance^2.
// ---------------------------------------------------------------------------
__global__ void sqrt_kernel(float* __restrict__ out, int offset) {
    int m = blockIdx.x * blockDim.x + threadIdx.x;
    if (m < MM) out[offset + m] = sqrtf(__uint_as_float(g_min[m]));
}

// ---------------------------------------------------------------------------
extern "C" void kernel_launch(void* const* d_in, const int* in_sizes, int n_in,
                              void* d_out, int out_size) {
    const float* embeds = (const float*)d_in[0];
    const float* cents  = (const float*)d_in[1];
    if (n_in >= 2 && in_sizes[0] == PP * DD && in_sizes[1] == MM * DD) {
        embeds = (const float*)d_in[1];
        cents  = (const float*)d_in[0];
    }
    float* out = (float*)d_out;
    int loss_elems = out_size - MM;
    if (loss_elems < 0) loss_elems = 0;

    cudaFuncSetAttribute(gemm_min_kernel,
                         cudaFuncAttributeMaxDynamicSharedMemorySize, SMEM_BYTES);

    prep_kernel<<<MM + PP, PT>>>(embeds, cents, out, loss_elems);
    gemm_min_kernel<<<GRID, THREADS, SMEM_BYTES>>>();
    sqrt_kernel<<<(MM + 255) / 256, 256>>>(out, loss_elems);
}